// round 15
// baseline (speedup 1.0000x reference)
#include <cuda_runtime.h>
#include <cuda_bf16.h>

// Problem constants
#define BB 4
#define LL 1024
#define HH 8
#define DD 512
#define DK 64
#define HB 32           // H*B
#define ML 4096         // B*L
#define LOG2E 1.4426950408889634f

// Scratch (allocation-free rule: __device__ globals).
__device__ __align__(16) float g_QP[ML * DD];
__device__ __align__(16) float g_KP[ML * DD];
__device__ __align__(16) float g_VP[ML * DD];
__device__ __align__(16) float g_OH[ML * DD];

// ---------------------------------------------------------------------------
// Double-buffered SGEMM body (PROVEN in R12, 498us). BM=128, BK=16, 256 thr.
//   BN=128, TN=8 (NT) / BN=64, TN=4 (NN). Split-half microtile, all smem
//   float4 accesses 16B-aligned (strides 132/68 floats).
// ---------------------------------------------------------------------------
template <int BN, int TN, bool BT>
__device__ __forceinline__ void gemm_big(const float* __restrict__ A, int lda,
                                         const float* __restrict__ Bm, int ldb,
                                         float* __restrict__ C, int ldc,
                                         int K, float alpha)
{
    __shared__ float As[2][16][128 + 4];
    __shared__ float Bs[2][16][BN + 4];

    const int tid = threadIdx.x;
    const int tx  = tid & 15;
    const int ty  = tid >> 4;
    const int m0  = blockIdx.y * 128;
    const int n0  = blockIdx.x * BN;

    const int arow = tid >> 1;
    const int ak   = (tid & 1) * 8;
    const int bkr  = tid >> 4;
    const int bnn  = (tid & 15) * 4;

    float4 a0, a1, b0, b1;

    a0 = *(const float4*)&A[(size_t)(m0 + arow) * lda + ak];
    a1 = *(const float4*)&A[(size_t)(m0 + arow) * lda + ak + 4];
    if (BT) {
        b0 = *(const float4*)&Bm[(size_t)(n0 + arow) * ldb + ak];
        b1 = *(const float4*)&Bm[(size_t)(n0 + arow) * ldb + ak + 4];
    } else {
        b0 = *(const float4*)&Bm[(size_t)bkr * ldb + n0 + bnn];
    }

    As[0][ak + 0][arow] = a0.x;  As[0][ak + 1][arow] = a0.y;
    As[0][ak + 2][arow] = a0.z;  As[0][ak + 3][arow] = a0.w;
    As[0][ak + 4][arow] = a1.x;  As[0][ak + 5][arow] = a1.y;
    As[0][ak + 6][arow] = a1.z;  As[0][ak + 7][arow] = a1.w;
    if (BT) {
        Bs[0][ak + 0][arow] = b0.x;  Bs[0][ak + 1][arow] = b0.y;
        Bs[0][ak + 2][arow] = b0.z;  Bs[0][ak + 3][arow] = b0.w;
        Bs[0][ak + 4][arow] = b1.x;  Bs[0][ak + 5][arow] = b1.y;
        Bs[0][ak + 6][arow] = b1.z;  Bs[0][ak + 7][arow] = b1.w;
    } else {
        *(float4*)&Bs[0][bkr][bnn] = b0;
    }
    __syncthreads();

    float acc[8][TN];
#pragma unroll
    for (int i = 0; i < 8; i++)
#pragma unroll
        for (int j = 0; j < TN; j++) acc[i][j] = 0.0f;

    const int nsteps = K >> 4;
    for (int s = 0; s < nsteps; s++) {
        const int cur = s & 1;
        const int nxt = cur ^ 1;
        const bool has = (s + 1 < nsteps);
        const int kn = (s + 1) << 4;

        if (has) {
            a0 = *(const float4*)&A[(size_t)(m0 + arow) * lda + kn + ak];
            a1 = *(const float4*)&A[(size_t)(m0 + arow) * lda + kn + ak + 4];
            if (BT) {
                b0 = *(const float4*)&Bm[(size_t)(n0 + arow) * ldb + kn + ak];
                b1 = *(const float4*)&Bm[(size_t)(n0 + arow) * ldb + kn + ak + 4];
            } else {
                b0 = *(const float4*)&Bm[(size_t)(kn + bkr) * ldb + n0 + bnn];
            }
        }

#pragma unroll
        for (int kk = 0; kk < 16; kk++) {
            float ar[8], br[TN];
            *(float4*)&ar[0] = *(const float4*)&As[cur][kk][ty * 4];
            *(float4*)&ar[4] = *(const float4*)&As[cur][kk][64 + ty * 4];
            *(float4*)&br[0] = *(const float4*)&Bs[cur][kk][tx * 4];
            if (TN == 8)
                *(float4*)&br[4] = *(const float4*)&Bs[cur][kk][64 + tx * 4];
#pragma unroll
            for (int i = 0; i < 8; i++)
#pragma unroll
                for (int j = 0; j < TN; j++)
                    acc[i][j] = fmaf(ar[i], br[j], acc[i][j]);
        }

        if (has) {
            As[nxt][ak + 0][arow] = a0.x;  As[nxt][ak + 1][arow] = a0.y;
            As[nxt][ak + 2][arow] = a0.z;  As[nxt][ak + 3][arow] = a0.w;
            As[nxt][ak + 4][arow] = a1.x;  As[nxt][ak + 5][arow] = a1.y;
            As[nxt][ak + 6][arow] = a1.z;  As[nxt][ak + 7][arow] = a1.w;
            if (BT) {
                Bs[nxt][ak + 0][arow] = b0.x;  Bs[nxt][ak + 1][arow] = b0.y;
                Bs[nxt][ak + 2][arow] = b0.z;  Bs[nxt][ak + 3][arow] = b0.w;
                Bs[nxt][ak + 4][arow] = b1.x;  Bs[nxt][ak + 5][arow] = b1.y;
                Bs[nxt][ak + 6][arow] = b1.z;  Bs[nxt][ak + 7][arow] = b1.w;
            } else {
                *(float4*)&Bs[nxt][bkr][bnn] = b0;
            }
            __syncthreads();
        }
    }

#pragma unroll
    for (int ih = 0; ih < 2; ih++) {
#pragma unroll
        for (int i = 0; i < 4; i++) {
            const size_t row =
                (size_t)(m0 + ih * 64 + ty * 4 + i) * ldc + n0;
#pragma unroll
            for (int jh = 0; jh < TN / 4; jh++) {
                float4 o = make_float4(acc[ih * 4 + i][jh * 4 + 0] * alpha,
                                       acc[ih * 4 + i][jh * 4 + 1] * alpha,
                                       acc[ih * 4 + i][jh * 4 + 2] * alpha,
                                       acc[ih * 4 + i][jh * 4 + 3] * alpha);
                *(float4*)&C[row + jh * 64 + tx * 4] = o;
            }
        }
    }
}

// ---------------------------------------------------------------------------
// GEMM wrappers (proven)
// ---------------------------------------------------------------------------
__global__ void __launch_bounds__(256, 2)
proj_kernel(const float* __restrict__ Q,
            const float* __restrict__ K,
            const float* __restrict__ V,
            const float* __restrict__ Wq,
            const float* __restrict__ Wk,
            const float* __restrict__ Wv)
{
    const float* A;
    const float* W;
    float* C;
    if (blockIdx.z == 0)      { A = Q; W = Wq; C = g_QP; }
    else if (blockIdx.z == 1) { A = K; W = Wk; C = g_KP; }
    else                      { A = V; W = Wv; C = g_VP; }
    gemm_big<128, 8, true>(A, DD, W, DD, C, DD, DD, 1.0f);
}

__global__ void __launch_bounds__(256, 2)
pv_kernel(const float* __restrict__ series)
{
    int z = blockIdx.z;
    int h = z >> 2;
    int b = z & 3;
    const float* A  = series + (size_t)z * LL * LL;
    const float* Bm = g_VP + (size_t)b * LL * DD + h * DK;
    float* C = g_OH + (size_t)b * LL * DD + h * DK;
    gemm_big<64, 4, false>(A, LL, Bm, DD, C, DD, LL, 1.0f);
}

__global__ void __launch_bounds__(256, 2)
outp_kernel(const float* __restrict__ Wo, float* __restrict__ out)
{
    gemm_big<128, 8, true>(g_OH, DD, Wo, DD, out, DD, DD, 1.0f);
}

// ---------------------------------------------------------------------------
// Fused scores + softmax. One CTA = 16 full rows (16 x 1024), K = 64.
// 256 threads: r = tid>>4 (row 0..15), cg = tid&15 (8-col group per n-tile).
// acc[nt][8]: nt = n-tile 0..7 (128 cols each), cols nt*128 + cg*8 .. +7.
// B tiles [k][n] (16 x 132 pitch, float4-aligned), double-buffered; A (16x64)
// resident in smem. After GEMM: scale by 1/8, row max via 16-lane shuffle,
// exp2, row sum, normalize, single float4-store pass. series written ONCE.
// ---------------------------------------------------------------------------
__global__ void __launch_bounds__(256, 2)
scores_softmax_kernel(float* __restrict__ series)
{
    __shared__ float As[16][68];
    __shared__ float Bs[2][16][132];

    const int z  = blockIdx.y;          // 0..31 (h*B+b)
    const int h  = z >> 2;
    const int b  = z & 3;
    const int m0 = blockIdx.x * 16;
    const float* Ag = g_QP + (size_t)b * LL * DD + h * DK;
    const float* Bg = g_KP + (size_t)b * LL * DD + h * DK;

    const int tid = threadIdx.x;
    const int r   = tid >> 4;           // 0..15
    const int cg  = tid & 15;           // 0..15

    // Stage A: 16 rows x 64 k (one float4 per thread)
    {
        const int ar = tid >> 4;
        const int a4 = (tid & 15) << 2;
        float4 v = *(const float4*)&Ag[(size_t)(m0 + ar) * DD + a4];
        As[ar][a4 + 0] = v.x;  As[ar][a4 + 1] = v.y;
        As[ar][a4 + 2] = v.z;  As[ar][a4 + 3] = v.w;
    }

    // B stage indices: col c = tid&127, k-half kh = tid>>7 (8 k each)
    const int bc = tid & 127;
    const int kh = (tid >> 7) * 8;

    // Prologue: stage step 0 (nt=0, kc=0) into buffer 0
    float4 s0 = *(const float4*)&Bg[(size_t)bc * DD + kh];
    float4 s1 = *(const float4*)&Bg[(size_t)bc * DD + kh + 4];
    Bs[0][kh + 0][bc] = s0.x;  Bs[0][kh + 1][bc] = s0.y;
    Bs[0][kh + 2][bc] = s0.z;  Bs[0][kh + 3][bc] = s0.w;
    Bs[0][kh + 4][bc] = s1.x;  Bs[0][kh + 5][bc] = s1.y;
    Bs[0][kh + 6][bc] = s1.z;  Bs[0][kh + 7][bc] = s1.w;
    __syncthreads();

    float acc[8][8];
#pragma unroll
    for (int i = 0; i < 8; i++)
#pragma unroll
        for (int j = 0; j < 8; j++) acc[i][j] = 0.0f;

    // 32 steps: step = nt*4 + kc  (nt: n-tile 0..7, kc: k-chunk 0..3)
    for (int s = 0; s < 32; s++) {
        const int cur = s & 1;
        const int nxt = cur ^ 1;
        const bool has = (s + 1 < 32);
        const int nt  = s >> 2;
        const int kc  = s & 3;

        if (has) {
            const int nn = (s + 1) >> 2;       // next n-tile
            const int nk = ((s + 1) & 3) * 16; // next k-chunk base
            s0 = *(const float4*)&Bg[(size_t)(nn * 128 + bc) * DD + nk + kh];
            s1 = *(const float4*)&Bg[(size_t)(nn * 128 + bc) * DD + nk + kh + 4];
        }

        const int kb = kc * 16;
#pragma unroll
        for (int k = 0; k < 16; k++) {
            float a = As[r][kb + k];
            float4 bv0 = *(const float4*)&Bs[cur][k][cg * 8];
            float4 bv1 = *(const float4*)&Bs[cur][k][cg * 8 + 4];
            acc[nt][0] = fmaf(a, bv0.x, acc[nt][0]);
            acc[nt][1] = fmaf(a, bv0.y, acc[nt][1]);
            acc[nt][2] = fmaf(a, bv0.z, acc[nt][2]);
            acc[nt][3] = fmaf(a, bv0.w, acc[nt][3]);
            acc[nt][4] = fmaf(a, bv1.x, acc[nt][4]);
            acc[nt][5] = fmaf(a, bv1.y, acc[nt][5]);
            acc[nt][6] = fmaf(a, bv1.z, acc[nt][6]);
            acc[nt][7] = fmaf(a, bv1.w, acc[nt][7]);
        }

        if (has) {
            Bs[nxt][kh + 0][bc] = s0.x;  Bs[nxt][kh + 1][bc] = s0.y;
            Bs[nxt][kh + 2][bc] = s0.z;  Bs[nxt][kh + 3][bc] = s0.w;
            Bs[nxt][kh + 4][bc] = s1.x;  Bs[nxt][kh + 5][bc] = s1.y;
            Bs[nxt][kh + 6][bc] = s1.z;  Bs[nxt][kh + 7][bc] = s1.w;
            __syncthreads();
        }
    }

    // Softmax over this thread's 64 cols + 16-lane row reduction.
    float mx = -3.4e38f;
#pragma unroll
    for (int i = 0; i < 8; i++)
#pragma unroll
        for (int j = 0; j < 8; j++) {
            acc[i][j] *= 0.125f;
            mx = fmaxf(mx, acc[i][j]);
        }
#pragma unroll
    for (int o = 8; o > 0; o >>= 1)
        mx = fmaxf(mx, __shfl_xor_sync(0xffffffffu, mx, o));

    float sum = 0.0f;
#pragma unroll
    for (int i = 0; i < 8; i++)
#pragma unroll
        for (int j = 0; j < 8; j++) {
            acc[i][j] = exp2f((acc[i][j] - mx) * LOG2E);
            sum += acc[i][j];
        }
#pragma unroll
    for (int o = 8; o > 0; o >>= 1)
        sum += __shfl_xor_sync(0xffffffffu, sum, o);
    const float inv = 1.0f / sum;

    // Write series once (two float4 per n-tile).
    const size_t rowb = ((size_t)z * LL + m0 + r) * LL;
#pragma unroll
    for (int nt = 0; nt < 8; nt++) {
        float4 o0 = make_float4(acc[nt][0] * inv, acc[nt][1] * inv,
                                acc[nt][2] * inv, acc[nt][3] * inv);
        float4 o1 = make_float4(acc[nt][4] * inv, acc[nt][5] * inv,
                                acc[nt][6] * inv, acc[nt][7] * inv);
        *(float4*)&series[rowb + nt * 128 + cg * 8]     = o0;
        *(float4*)&series[rowb + nt * 128 + cg * 8 + 4] = o1;
    }
}

// ---------------------------------------------------------------------------
// Block reduction (256 threads) for prior.
// ---------------------------------------------------------------------------
__device__ __forceinline__ float block_reduce_sum(float v)
{
    __shared__ float red[8];
#pragma unroll
    for (int o = 16; o > 0; o >>= 1)
        v += __shfl_xor_sync(0xffffffffu, v, o);
    int lane = threadIdx.x & 31;
    int wrp  = threadIdx.x >> 5;
    if (lane == 0) red[wrp] = v;
    __syncthreads();
    float r = red[0];
#pragma unroll
    for (int i = 1; i < 8; i++) r += red[i];
    return r;
}

// ---------------------------------------------------------------------------
// Prior (unchanged from 498us kernel).
// ---------------------------------------------------------------------------
__global__ void prior_kernel(const float* __restrict__ Sigma,
                             const float* __restrict__ Wsig,
                             float* __restrict__ prior)
{
    int r  = blockIdx.x;
    int i  = r & (LL - 1);
    int hb = r >> 10;
    int h  = hb >> 2;
    int b  = hb & 3;

    float sig = 0.0f;
#pragma unroll
    for (int k = 0; k < HH; k++)
        sig = fmaf(Sigma[((size_t)(b * LL + i)) * HH + k], Wsig[h * HH + k], sig);

    float t = -LOG2E / (2.0f * sig * sig);

    int j0 = threadIdx.x * 4;
    float v[4];
    float s = 0.0f;
#pragma unroll
    for (int u = 0; u < 4; u++) {
        float d = (float)(i - (j0 + u));
        v[u] = exp2f(d * d * t);
        s += v[u];
    }
    float tot = block_reduce_sum(s);
    float inv = 1.0f / tot;
    float4 o = make_float4(v[0] * inv, v[1] * inv, v[2] * inv, v[3] * inv);
    *(float4*)&prior[(size_t)r * LL + j0] = o;
}

// ---------------------------------------------------------------------------
// Launch.  d_out: prior[32M] | series[32M] | out[2M] floats
// ---------------------------------------------------------------------------
extern "C" void kernel_launch(void* const* d_in, const int* in_sizes, int n_in,
                              void* d_out, int out_size)
{
    const float* Sigma = (const float*)d_in[0];
    const float* Q     = (const float*)d_in[1];
    const float* K     = (const float*)d_in[2];
    const float* V     = (const float*)d_in[3];
    const float* Wsig  = (const float*)d_in[4];
    const float* Wq    = (const float*)d_in[5];
    const float* Wk    = (const float*)d_in[6];
    const float* Wv    = (const float*)d_in[7];
    const float* Wo    = (const float*)d_in[8];

    float* prior  = (float*)d_out;
    float* series = prior + (size_t)HB * LL * LL;
    float* obuf   = series + (size_t)HB * LL * LL;

    // Prior path (independent)
    prior_kernel<<<HB * LL, 256>>>(Sigma, Wsig, prior);

    // Projections
    proj_kernel<<<dim3(DD / 128, ML / 128, 3), 256>>>(Q, K, V, Wq, Wk, Wv);

    // Fused scores + softmax (writes normalized series once)
    scores_softmax_kernel<<<dim3(LL / 16, HB), 256>>>(series);

    // PV
    pv_kernel<<<dim3(DK / 64, LL / 128, HB), 256>>>(series);

    // Output projection
    outp_kernel<<<dim3(DD / 128, ML / 128, 1), 256>>>(Wo, obuf);
}

// round 17
// speedup vs baseline: 1.9735x; 1.9735x over previous
#include <cuda_runtime.h>
#include <cuda_bf16.h>

// Problem constants
#define BB 4
#define LL 1024
#define HH 8
#define DD 512
#define DK 64
#define HB 32           // H*B
#define ML 4096         // B*L
#define LOG2E 1.4426950408889634f
#define NSPLIT 4

// Scratch (allocation-free rule: __device__ globals).
__device__ __align__(16) float g_QP[ML * DD];
__device__ __align__(16) float g_KP[ML * DD];
__device__ __align__(16) float g_VP[ML * DD];
__device__ __align__(16) float g_OHS[NSPLIT * ML * DD];   // pv split-K outputs

// ---------------------------------------------------------------------------
// Double-buffered SGEMM body (PROVEN at 498us). BM=128, BK=16, 256 threads.
//   BN=128, TN=8 (NT) / BN=64, TN=4 (NN). Split-half microtile; all smem
//   float4 accesses 16B-aligned (strides 132/68 floats).
// ---------------------------------------------------------------------------
template <int BN, int TN, bool BT>
__device__ __forceinline__ void gemm_big(const float* __restrict__ A, int lda,
                                         const float* __restrict__ Bm, int ldb,
                                         float* __restrict__ C, int ldc,
                                         int K, float alpha)
{
    __shared__ float As[2][16][128 + 4];
    __shared__ float Bs[2][16][BN + 4];

    const int tid = threadIdx.x;
    const int tx  = tid & 15;
    const int ty  = tid >> 4;
    const int m0  = blockIdx.y * 128;
    const int n0  = blockIdx.x * BN;

    const int arow = tid >> 1;
    const int ak   = (tid & 1) * 8;
    const int bkr  = tid >> 4;
    const int bnn  = (tid & 15) * 4;

    float4 a0, a1, b0, b1;

    a0 = *(const float4*)&A[(size_t)(m0 + arow) * lda + ak];
    a1 = *(const float4*)&A[(size_t)(m0 + arow) * lda + ak + 4];
    if (BT) {
        b0 = *(const float4*)&Bm[(size_t)(n0 + arow) * ldb + ak];
        b1 = *(const float4*)&Bm[(size_t)(n0 + arow) * ldb + ak + 4];
    } else {
        b0 = *(const float4*)&Bm[(size_t)bkr * ldb + n0 + bnn];
    }

    As[0][ak + 0][arow] = a0.x;  As[0][ak + 1][arow] = a0.y;
    As[0][ak + 2][arow] = a0.z;  As[0][ak + 3][arow] = a0.w;
    As[0][ak + 4][arow] = a1.x;  As[0][ak + 5][arow] = a1.y;
    As[0][ak + 6][arow] = a1.z;  As[0][ak + 7][arow] = a1.w;
    if (BT) {
        Bs[0][ak + 0][arow] = b0.x;  Bs[0][ak + 1][arow] = b0.y;
        Bs[0][ak + 2][arow] = b0.z;  Bs[0][ak + 3][arow] = b0.w;
        Bs[0][ak + 4][arow] = b1.x;  Bs[0][ak + 5][arow] = b1.y;
        Bs[0][ak + 6][arow] = b1.z;  Bs[0][ak + 7][arow] = b1.w;
    } else {
        *(float4*)&Bs[0][bkr][bnn] = b0;
    }
    __syncthreads();

    float acc[8][TN];
#pragma unroll
    for (int i = 0; i < 8; i++)
#pragma unroll
        for (int j = 0; j < TN; j++) acc[i][j] = 0.0f;

    const int nsteps = K >> 4;
    for (int s = 0; s < nsteps; s++) {
        const int cur = s & 1;
        const int nxt = cur ^ 1;
        const bool has = (s + 1 < nsteps);
        const int kn = (s + 1) << 4;

        if (has) {
            a0 = *(const float4*)&A[(size_t)(m0 + arow) * lda + kn + ak];
            a1 = *(const float4*)&A[(size_t)(m0 + arow) * lda + kn + ak + 4];
            if (BT) {
                b0 = *(const float4*)&Bm[(size_t)(n0 + arow) * ldb + kn + ak];
                b1 = *(const float4*)&Bm[(size_t)(n0 + arow) * ldb + kn + ak + 4];
            } else {
                b0 = *(const float4*)&Bm[(size_t)(kn + bkr) * ldb + n0 + bnn];
            }
        }

#pragma unroll
        for (int kk = 0; kk < 16; kk++) {
            float ar[8], br[TN];
            *(float4*)&ar[0] = *(const float4*)&As[cur][kk][ty * 4];
            *(float4*)&ar[4] = *(const float4*)&As[cur][kk][64 + ty * 4];
            *(float4*)&br[0] = *(const float4*)&Bs[cur][kk][tx * 4];
            if (TN == 8)
                *(float4*)&br[4] = *(const float4*)&Bs[cur][kk][64 + tx * 4];
#pragma unroll
            for (int i = 0; i < 8; i++)
#pragma unroll
                for (int j = 0; j < TN; j++)
                    acc[i][j] = fmaf(ar[i], br[j], acc[i][j]);
        }

        if (has) {
            As[nxt][ak + 0][arow] = a0.x;  As[nxt][ak + 1][arow] = a0.y;
            As[nxt][ak + 2][arow] = a0.z;  As[nxt][ak + 3][arow] = a0.w;
            As[nxt][ak + 4][arow] = a1.x;  As[nxt][ak + 5][arow] = a1.y;
            As[nxt][ak + 6][arow] = a1.z;  As[nxt][ak + 7][arow] = a1.w;
            if (BT) {
                Bs[nxt][ak + 0][arow] = b0.x;  Bs[nxt][ak + 1][arow] = b0.y;
                Bs[nxt][ak + 2][arow] = b0.z;  Bs[nxt][ak + 3][arow] = b0.w;
                Bs[nxt][ak + 4][arow] = b1.x;  Bs[nxt][ak + 5][arow] = b1.y;
                Bs[nxt][ak + 6][arow] = b1.z;  Bs[nxt][ak + 7][arow] = b1.w;
            } else {
                *(float4*)&Bs[nxt][bkr][bnn] = b0;
            }
            __syncthreads();
        }
    }

#pragma unroll
    for (int ih = 0; ih < 2; ih++) {
#pragma unroll
        for (int i = 0; i < 4; i++) {
            const size_t row =
                (size_t)(m0 + ih * 64 + ty * 4 + i) * ldc + n0;
#pragma unroll
            for (int jh = 0; jh < TN / 4; jh++) {
                float4 o = make_float4(acc[ih * 4 + i][jh * 4 + 0] * alpha,
                                       acc[ih * 4 + i][jh * 4 + 1] * alpha,
                                       acc[ih * 4 + i][jh * 4 + 2] * alpha,
                                       acc[ih * 4 + i][jh * 4 + 3] * alpha);
                *(float4*)&C[row + jh * 64 + tx * 4] = o;
            }
        }
    }
}

// ---------------------------------------------------------------------------
// GEMM wrappers
// ---------------------------------------------------------------------------
__global__ void __launch_bounds__(256, 2)
proj_kernel(const float* __restrict__ Q,
            const float* __restrict__ K,
            const float* __restrict__ V,
            const float* __restrict__ Wq,
            const float* __restrict__ Wk,
            const float* __restrict__ Wv)
{
    const float* A;
    const float* W;
    float* C;
    if (blockIdx.z == 0)      { A = Q; W = Wq; C = g_QP; }
    else if (blockIdx.z == 1) { A = K; W = Wk; C = g_KP; }
    else                      { A = V; W = Wv; C = g_VP; }
    gemm_big<128, 8, true>(A, DD, W, DD, C, DD, DD, 1.0f);
}

// scores (proven): per z, S = (Qh Kh^T)/8, M=N=1024, K=64
__global__ void __launch_bounds__(256, 2)
scores_kernel(float* __restrict__ series)
{
    int z = blockIdx.z;
    int h = z >> 2;
    int b = z & 3;
    const float* A  = g_QP + (size_t)b * LL * DD + h * DK;
    const float* Bm = g_KP + (size_t)b * LL * DD + h * DK;
    float* C = series + (size_t)z * LL * LL;
    gemm_big<128, 8, true>(A, DD, Bm, DD, C, LL, DK, 0.125f);
}

// PV split-K: blockIdx.z = split*HB + z. Each split covers K=256 of the
// m-sum, writing its own g_OHS slot (grid 1024 CTAs -> 4x occupancy of R12).
__global__ void __launch_bounds__(256, 2)
pv_kernel(const float* __restrict__ series)
{
    int zz    = blockIdx.z;
    int split = zz >> 5;          // 0..3
    int z     = zz & 31;          // h*B+b
    int h = z >> 2;
    int b = z & 3;
    const int k0 = split * (LL / NSPLIT);
    const float* A  = series + (size_t)z * LL * LL + k0;
    const float* Bm = g_VP + (size_t)b * LL * DD + h * DK + (size_t)k0 * DD;
    float* C = g_OHS + (size_t)split * ML * DD + (size_t)b * LL * DD + h * DK;
    gemm_big<64, 4, false>(A, LL, Bm, DD, C, DD, LL / NSPLIT, 1.0f);
}

// Sum the 4 pv splits in place into slot 0 (read 32MB, write 8MB).
__global__ void __launch_bounds__(256)
reduce_oh_kernel()
{
    const size_t n4 = (size_t)ML * DD / 4;
    size_t i = (size_t)blockIdx.x * blockDim.x + threadIdx.x;
    if (i >= n4) return;
    float4* p = (float4*)g_OHS;
    const size_t stride = n4;     // one slot in float4 units
    float4 s0 = p[i];
    float4 s1 = p[i + stride];
    float4 s2 = p[i + 2 * stride];
    float4 s3 = p[i + 3 * stride];
    s0.x += s1.x + s2.x + s3.x;
    s0.y += s1.y + s2.y + s3.y;
    s0.z += s1.z + s2.z + s3.z;
    s0.w += s1.w + s2.w + s3.w;
    p[i] = s0;
}

// out = OH @ Wo^T (reads reduced slot 0 of g_OHS)
__global__ void __launch_bounds__(256, 2)
outp_kernel(const float* __restrict__ Wo, float* __restrict__ out)
{
    gemm_big<128, 8, true>(g_OHS, DD, Wo, DD, out, DD, DD, 1.0f);
}

// ---------------------------------------------------------------------------
// Block reductions (256 threads = 8 warps) for prior/softmax.
// ---------------------------------------------------------------------------
template <int OP>  // 0 = sum, 1 = max
__device__ __forceinline__ float block_reduce(float v)
{
    __shared__ float red[8];
#pragma unroll
    for (int o = 16; o > 0; o >>= 1) {
        float w = __shfl_xor_sync(0xffffffffu, v, o);
        v = (OP == 1) ? fmaxf(v, w) : (v + w);
    }
    int lane = threadIdx.x & 31;
    int wrp  = threadIdx.x >> 5;
    if (lane == 0) red[wrp] = v;
    __syncthreads();
    float r = red[0];
#pragma unroll
    for (int i = 1; i < 8; i++) r = (OP == 1) ? fmaxf(r, red[i]) : (r + red[i]);
    return r;
}

// ---------------------------------------------------------------------------
// Prior (proven).
// ---------------------------------------------------------------------------
__global__ void prior_kernel(const float* __restrict__ Sigma,
                             const float* __restrict__ Wsig,
                             float* __restrict__ prior)
{
    int r  = blockIdx.x;
    int i  = r & (LL - 1);
    int hb = r >> 10;
    int h  = hb >> 2;
    int b  = hb & 3;

    float sig = 0.0f;
#pragma unroll
    for (int k = 0; k < HH; k++)
        sig = fmaf(Sigma[((size_t)(b * LL + i)) * HH + k], Wsig[h * HH + k], sig);

    float t = -LOG2E / (2.0f * sig * sig);

    int j0 = threadIdx.x * 4;
    float v[4];
    float s = 0.0f;
#pragma unroll
    for (int u = 0; u < 4; u++) {
        float d = (float)(i - (j0 + u));
        v[u] = exp2f(d * d * t);
        s += v[u];
    }
    float tot = block_reduce<0>(s);
    float inv = 1.0f / tot;
    float4 o = make_float4(v[0] * inv, v[1] * inv, v[2] * inv, v[3] * inv);
    *(float4*)&prior[(size_t)r * LL + j0] = o;
}

// ---------------------------------------------------------------------------
// Softmax in-place (proven).
// ---------------------------------------------------------------------------
__global__ void softmax_kernel(float* __restrict__ series)
{
    size_t base = (size_t)blockIdx.x * LL;
    int j0 = threadIdx.x * 4;
    float4 sv = *(const float4*)&series[base + j0];
    float s[4] = {sv.x, sv.y, sv.z, sv.w};

    float mx = fmaxf(fmaxf(s[0], s[1]), fmaxf(s[2], s[3]));
    mx = block_reduce<1>(mx);

    float e[4];
    float sum = 0.0f;
#pragma unroll
    for (int u = 0; u < 4; u++) {
        e[u] = exp2f((s[u] - mx) * LOG2E);
        sum += e[u];
    }
    __syncthreads();
    sum = block_reduce<0>(sum);
    float inv = 1.0f / sum;
    float4 o = make_float4(e[0] * inv, e[1] * inv, e[2] * inv, e[3] * inv);
    *(float4*)&series[base + j0] = o;
}

// ---------------------------------------------------------------------------
// Launch.  d_out: prior[32M] | series[32M] | out[2M] floats
// ---------------------------------------------------------------------------
extern "C" void kernel_launch(void* const* d_in, const int* in_sizes, int n_in,
                              void* d_out, int out_size)
{
    const float* Sigma = (const float*)d_in[0];
    const float* Q     = (const float*)d_in[1];
    const float* K     = (const float*)d_in[2];
    const float* V     = (const float*)d_in[3];
    const float* Wsig  = (const float*)d_in[4];
    const float* Wq    = (const float*)d_in[5];
    const float* Wk    = (const float*)d_in[6];
    const float* Wv    = (const float*)d_in[7];
    const float* Wo    = (const float*)d_in[8];

    float* prior  = (float*)d_out;
    float* series = prior + (size_t)HB * LL * LL;
    float* obuf   = series + (size_t)HB * LL * LL;

    // Prior path (independent)
    prior_kernel<<<HB * LL, 256>>>(Sigma, Wsig, prior);

    // Projections
    proj_kernel<<<dim3(DD / 128, ML / 128, 3), 256>>>(Q, K, V, Wq, Wk, Wv);

    // Attention (proven separate scores + softmax)
    scores_kernel<<<dim3(LL / 128, LL / 128, HB), 256>>>(series);
    softmax_kernel<<<HB * LL, 256>>>(series);

    // PV split-K x4 + reduce
    pv_kernel<<<dim3(DK / 64, LL / 128, HB * NSPLIT), 256>>>(series);
    reduce_oh_kernel<<<(ML * DD / 4 + 255) / 256, 256>>>();

    // Output projection
    outp_kernel<<<dim3(DD / 128, ML / 128, 1), 256>>>(Wo, obuf);
}